// round 2
// baseline (speedup 1.0000x reference)
#include <cuda_runtime.h>
#include <math.h>

typedef unsigned long long ull;

#define RANK     64
#define WIN      11
#define PAD      5
#define TR       64
#define NTHREADS 256
#define STRIDE   68                 // padded row stride (floats) for tf / v1 tiles
#define TFROWS   (TR + 2*PAD)       // 74

// dynamic smem layout (floats):
//  s_tf : TFROWS*STRIDE = 5032
//  s_wp : 32*64 ull     = 4096 floats (k-pair-interleaved W)
//  s_v1 : TR*STRIDE     = 4352
//  s_b  : 64
#define SMEM_FLOATS (TFROWS*STRIDE + 4096 + TR*STRIDE + RANK)
#define SMEM_BYTES  (SMEM_FLOATS * 4)

__device__ __forceinline__ ull pack2(float lo, float hi) {
    ull r; asm("mov.b64 %0,{%1,%2};" : "=l"(r) : "f"(lo), "f"(hi)); return r;
}
__device__ __forceinline__ void unpack2(ull v, float& lo, float& hi) {
    asm("mov.b64 {%0,%1},%2;" : "=f"(lo), "=f"(hi) : "l"(v));
}
__device__ __forceinline__ ull fma2(ull a, ull b, ull c) {
    ull d; asm("fma.rn.f32x2 %0,%1,%2,%3;" : "=l"(d) : "l"(a), "l"(b), "l"(c)); return d;
}
__device__ __forceinline__ ull mul2(ull a, ull b) {
    ull d; asm("mul.rn.f32x2 %0,%1,%2;" : "=l"(d) : "l"(a), "l"(b)); return d;
}

__global__ void __launch_bounds__(NTHREADS, 2)
attn_win_kernel(const float* __restrict__ tf, const float* __restrict__ Wm,
                const float* __restrict__ bv, float* __restrict__ out, int nrows)
{
    extern __shared__ float smem[];
    float* s_tf = smem;                                    // [74][68]
    ull*   s_wp = (ull*)(smem + TFROWS*STRIDE);            // [32][64]  (kp, c) pairs
    float* s_v1 = smem + TFROWS*STRIDE + 4096;             // [64][68]
    float* s_b  = s_v1 + TR*STRIDE;                        // [64]

    const int tid = threadIdx.x;
    const int gr0 = blockIdx.x * TR;

    // ---- prologue: stage W (k-pair interleaved), b, tf tile (+halo, zero-padded) ----
    for (int idx = tid; idx < RANK*16; idx += NTHREADS) {
        int c = idx & 63, q = idx >> 6;                    // q = k/4 chunk, 0..15
        float4 v = *(const float4*)(Wm + c*RANK + q*4);
        s_wp[(2*q  )*RANK + c] = pack2(v.x, v.y);          // (W[c][2kp], W[c][2kp+1])
        s_wp[(2*q+1)*RANK + c] = pack2(v.z, v.w);
    }
    if (tid < RANK) s_b[tid] = bv[tid];
    for (int idx = tid; idx < TFROWS*16; idx += NTHREADS) {
        int i = idx >> 4, q = idx & 15;
        int grow = gr0 - PAD + i;
        float4 v = make_float4(0.f, 0.f, 0.f, 0.f);
        if (grow >= 0 && grow < nrows)
            v = *(const float4*)(tf + (size_t)grow*RANK + q*4);
        *(float4*)(s_tf + i*STRIDE + q*4) = v;
    }
    __syncthreads();

    // ---- phase 1: var1 = tanh(tf @ W^T + b), 4x4 micro-tile, f32x2 over K pairs ----
    {
        const int rgrp = tid >> 4;          // rows 4*rgrp..+3
        const int cgrp = tid & 15;          // cols 4*cgrp..+3
        const float* a0 = s_tf + (4*rgrp + PAD)*STRIDE;
        const ull*   wb = s_wp + 4*cgrp;
        ull acc[4][4];
        #pragma unroll
        for (int i = 0; i < 4; i++)
            #pragma unroll
            for (int j = 0; j < 4; j++) acc[i][j] = 0ULL;

        #pragma unroll 4
        for (int kp = 0; kp < RANK/2; kp++) {
            ull a[4], w[4];
            #pragma unroll
            for (int i = 0; i < 4; i++)
                a[i] = *(const ull*)(a0 + i*STRIDE + 2*kp);   // (tf[r][2kp], tf[r][2kp+1])
            ulonglong2 wA = *(const ulonglong2*)(wb + kp*RANK);
            ulonglong2 wB = *(const ulonglong2*)(wb + kp*RANK + 2);
            w[0] = wA.x; w[1] = wA.y; w[2] = wB.x; w[3] = wB.y;
            #pragma unroll
            for (int i = 0; i < 4; i++)
                #pragma unroll
                for (int j = 0; j < 4; j++)
                    acc[i][j] = fma2(a[i], w[j], acc[i][j]); // even/odd-k partials
        }
        float4 bb = *(const float4*)(s_b + 4*cgrp);
        #pragma unroll
        for (int i = 0; i < 4; i++) {
            float lo, hi; float4 r;
            unpack2(acc[i][0], lo, hi); r.x = tanhf(lo + hi + bb.x);
            unpack2(acc[i][1], lo, hi); r.y = tanhf(lo + hi + bb.y);
            unpack2(acc[i][2], lo, hi); r.z = tanhf(lo + hi + bb.z);
            unpack2(acc[i][3], lo, hi); r.w = tanhf(lo + hi + bb.w);
            *(float4*)(s_v1 + (4*rgrp + i)*STRIDE + 4*cgrp) = r;
        }
    }
    __syncthreads();

    // ---- phase 2: window dots + online softmax + weighted sum (single SMEM pass) ----
    {
        const int lr   = tid >> 2;          // local row 0..63
        const int part = tid & 3;           // 16-channel chunk
        const int c0   = part * 16;

        ull v1p[8];
        #pragma unroll
        for (int i = 0; i < 4; i++) {
            ulonglong2 t = *(const ulonglong2*)(s_v1 + lr*STRIDE + c0 + 4*i);
            v1p[2*i] = t.x; v1p[2*i+1] = t.y;
        }

        float m = -1e30f, ssum = 0.f;
        ull o[8];
        #pragma unroll
        for (int i = 0; i < 8; i++) o[i] = 0ULL;

        #pragma unroll
        for (int w = 0; w < WIN; w++) {
            const float* trow = s_tf + (lr + w)*STRIDE + c0;  // = global row gr+w-5
            ull tp[8];
            #pragma unroll
            for (int i = 0; i < 4; i++) {
                ulonglong2 t = *(const ulonglong2*)(trow + 4*i);
                tp[2*i] = t.x; tp[2*i+1] = t.y;
            }
            ull dp = 0ULL;
            #pragma unroll
            for (int i = 0; i < 8; i++) dp = fma2(tp[i], v1p[i], dp);
            float dlo, dhi; unpack2(dp, dlo, dhi);
            float d = dlo + dhi;
            d += __shfl_xor_sync(0xffffffffu, d, 1);   // reduce across the 4
            d += __shfl_xor_sync(0xffffffffu, d, 2);   // channel-chunk lanes
            d *= 0.125f;                               // / sqrt(64)

            float mnew = fmaxf(m, d);
            float corr = __expf(m - mnew);             // first iter: exp(-huge)=0
            float e    = __expf(d - mnew);
            ssum = ssum * corr + e;
            ull c2 = pack2(corr, corr), e2 = pack2(e, e);
            #pragma unroll
            for (int i = 0; i < 8; i++)
                o[i] = fma2(tp[i], e2, mul2(o[i], c2));
            m = mnew;
        }

        int gr = gr0 + lr;
        if (gr < nrows) {
            float rs = 1.0f / ssum;
            #pragma unroll
            for (int i = 0; i < 4; i++) {
                float lo, hi; float4 r;
                unpack2(o[2*i],   lo, hi); r.x = lo*rs; r.y = hi*rs;
                unpack2(o[2*i+1], lo, hi); r.z = lo*rs; r.w = hi*rs;
                *(float4*)(out + (size_t)gr*RANK + c0 + 4*i) = r;
            }
        }
    }
}

extern "C" void kernel_launch(void* const* d_in, const int* in_sizes, int n_in,
                              void* d_out, int out_size)
{
    const float* tf = (const float*)d_in[0];   // time_factor (L, 64)
    const float* Wm = (const float*)d_in[1];   // W (64, 64)
    const float* bv = (const float*)d_in[2];   // b (64,)
    float* out = (float*)d_out;
    int nrows = in_sizes[0] / RANK;

    cudaFuncSetAttribute(attn_win_kernel,
                         cudaFuncAttributeMaxDynamicSharedMemorySize, SMEM_BYTES);
    int grid = (nrows + TR - 1) / TR;
    attn_win_kernel<<<grid, NTHREADS, SMEM_BYTES>>>(tf, Wm, bv, out, nrows);
}

// round 9
// speedup vs baseline: 1.3779x; 1.3779x over previous
#include <cuda_runtime.h>
#include <cuda_bf16.h>
#include <cstdint>
#include <math.h>

typedef unsigned long long ull;

#define RANK   64
#define WIN    11
#define PAD    5
#define TR     128
#define NT     128
#define STRIDE 68
#define TFROWS (TR + 2*PAD)   // 138

// byte offsets in dynamic smem
#define OFF_TF   0                       // [138][68] f32 = 37536
#define OFF_V1   37536                   // [128][68] f32 raw GEMM acc = 34816
#define OFF_WH   72352                   // [64][72] bf16 hi = 9216
#define OFF_WL   81568                   // [64][72] bf16 lo = 9216
#define OFF_BIAS 90784                   // 32 ull packed pairs = 256
#define SMEM_TOTAL 91040
#define WROW 144                         // W tile row stride bytes (72 bf16)

__device__ __forceinline__ ull pack2(float lo, float hi) {
    ull r; asm("mov.b64 %0,{%1,%2};" : "=l"(r) : "f"(lo), "f"(hi)); return r;
}
__device__ __forceinline__ void unpack2(ull v, float& lo, float& hi) {
    asm("mov.b64 {%0,%1},%2;" : "=f"(lo), "=f"(hi) : "l"(v));
}
__device__ __forceinline__ ull fma2(ull a, ull b, ull c) {
    ull d; asm("fma.rn.f32x2 %0,%1,%2,%3;" : "=l"(d) : "l"(a), "l"(b), "l"(c)); return d;
}
__device__ __forceinline__ ull add2(ull a, ull b) {
    ull d; asm("add.rn.f32x2 %0,%1,%2;" : "=l"(d) : "l"(a), "l"(b)); return d;
}
// pack (lo, hi) floats into bf16x2 (lo -> lower 16 bits)
__device__ __forceinline__ uint32_t bf2(float lo, float hi) {
    uint32_t r; asm("cvt.rn.bf16x2.f32 %0, %1, %2;" : "=r"(r) : "f"(hi), "f"(lo)); return r;
}
// hi/lo split of a float pair into two bf16x2 regs
__device__ __forceinline__ void split2(float f0, float f1, uint32_t& h, uint32_t& l) {
    h = bf2(f0, f1);
    float f0h = __uint_as_float(h << 16);
    float f1h = __uint_as_float(h & 0xffff0000u);
    l = bf2(f0 - f0h, f1 - f1h);
}
__device__ __forceinline__ float tanh_fast(float x) {
    float e = __expf(2.f * x);
    return 1.f - __fdividef(2.f, e + 1.f);
}

#define MMA(Cr, Ar, b0, b1)                                                    \
    asm volatile(                                                              \
        "mma.sync.aligned.m16n8k16.row.col.f32.bf16.bf16.f32 "                 \
        "{%0,%1,%2,%3},{%4,%5,%6,%7},{%8,%9},{%0,%1,%2,%3};"                   \
        : "+f"(Cr[0]), "+f"(Cr[1]), "+f"(Cr[2]), "+f"(Cr[3])                   \
        : "r"(Ar[0]), "r"(Ar[1]), "r"(Ar[2]), "r"(Ar[3]), "r"(b0), "r"(b1))

__global__ void __launch_bounds__(NT, 2)
attn_win_kernel(const float* __restrict__ tf, const float* __restrict__ Wm,
                const float* __restrict__ bv, float* __restrict__ out, int nrows)
{
    extern __shared__ char smem[];
    float* s_tf   = (float*)(smem + OFF_TF);
    float* s_v1   = (float*)(smem + OFF_V1);
    ull*   s_bias = (ull*)(smem + OFF_BIAS);
    const int tid = threadIdx.x;
    const int wid = tid >> 5;
    const int lane = tid & 31;
    const int gr0 = blockIdx.x * TR;

    // ---- stage tf tile (fp32, zero-padded halo) ----
    for (int idx = tid; idx < TFROWS * 16; idx += NT) {
        int i = idx >> 4, q = idx & 15;
        int grow = gr0 - PAD + i;
        float4 v = make_float4(0.f, 0.f, 0.f, 0.f);
        if (grow >= 0 && grow < nrows)
            v = *(const float4*)(tf + (size_t)grow * RANK + 4 * q);
        *(float4*)(s_tf + i * STRIDE + 4 * q) = v;
    }
    // ---- stage W hi/lo bf16 tiles (row stride 72 bf16) ----
    for (int idx = tid; idx < 64 * 32; idx += NT) {
        int c = idx >> 5, kp = idx & 31;
        float2 wv = *(const float2*)(Wm + c * RANK + 2 * kp);
        uint32_t h, l; split2(wv.x, wv.y, h, l);
        *(uint32_t*)(smem + OFF_WH + c * WROW + kp * 4) = h;
        *(uint32_t*)(smem + OFF_WL + c * WROW + kp * 4) = l;
    }
    if (tid < RANK / 2) {
        float2 bp = *(const float2*)(bv + 2 * tid);
        s_bias[tid] = pack2(bp.x, bp.y);
    }
    __syncthreads();

    // ---- phase 1: raw var1 = tf @ W^T via 3-term bf16-split HMMA ----
    {
        const int g = lane >> 2, t = lane & 3;
        float C[2][8][4];
        #pragma unroll
        for (int mt = 0; mt < 2; mt++)
            #pragma unroll
            for (int nt = 0; nt < 8; nt++)
                #pragma unroll
                for (int j = 0; j < 4; j++) C[mt][nt][j] = 0.f;

        #pragma unroll
        for (int ks = 0; ks < 4; ks++) {
            uint32_t AH[2][4], AL[2][4];
            #pragma unroll
            for (int mt = 0; mt < 2; mt++) {
                const float* a0 = s_tf + (32 * wid + 16 * mt + g + PAD) * STRIDE
                                 + ks * 16 + 2 * t;
                float2 a00 = *(const float2*)(a0);
                float2 a01 = *(const float2*)(a0 + 8);
                float2 a10 = *(const float2*)(a0 + 8 * STRIDE);
                float2 a11 = *(const float2*)(a0 + 8 * STRIDE + 8);
                split2(a00.x, a00.y, AH[mt][0], AL[mt][0]);
                split2(a10.x, a10.y, AH[mt][1], AL[mt][1]);
                split2(a01.x, a01.y, AH[mt][2], AL[mt][2]);
                split2(a11.x, a11.y, AH[mt][3], AL[mt][3]);
            }
            #pragma unroll
            for (int nt = 0; nt < 8; nt++) {
                const char* wb = smem + OFF_WH + (nt * 8 + g) * WROW
                                 + (ks * 16 + 2 * t) * 2;
                uint32_t bh0 = *(const uint32_t*)(wb);
                uint32_t bh1 = *(const uint32_t*)(wb + 16);
                uint32_t bl0 = *(const uint32_t*)(wb + (OFF_WL - OFF_WH));
                uint32_t bl1 = *(const uint32_t*)(wb + (OFF_WL - OFF_WH) + 16);
                #pragma unroll
                for (int mt = 0; mt < 2; mt++) {
                    MMA(C[mt][nt], AH[mt], bh0, bh1);
                    MMA(C[mt][nt], AH[mt], bl0, bl1);
                    MMA(C[mt][nt], AL[mt], bh0, bh1);
                }
            }
        }
        // epilogue: raw accumulators -> s_v1
        #pragma unroll
        for (int mt = 0; mt < 2; mt++) {
            #pragma unroll
            for (int nt = 0; nt < 8; nt++) {
                float* vp = s_v1 + (32 * wid + 16 * mt + g) * STRIDE + nt * 8 + 2 * t;
                *(float2*)(vp)              = make_float2(C[mt][nt][0], C[mt][nt][1]);
                *(float2*)(vp + 8 * STRIDE) = make_float2(C[mt][nt][2], C[mt][nt][3]);
            }
        }
    }
    __syncthreads();

    // ---- phase 2: bias+tanh, window dots, max-free softmax, weighted sum ----
    {
        ull v1[32];
        #pragma unroll
        for (int i = 0; i < 16; i++) {
            ulonglong2 tv = *(const ulonglong2*)(s_v1 + tid * STRIDE + 4 * i);
            ull s0 = add2(tv.x, s_bias[2 * i]);
            ull s1 = add2(tv.y, s_bias[2 * i + 1]);
            float x0, x1, x2, x3;
            unpack2(s0, x0, x1); unpack2(s1, x2, x3);
            v1[2 * i]     = pack2(tanh_fast(x0), tanh_fast(x1));
            v1[2 * i + 1] = pack2(tanh_fast(x2), tanh_fast(x3));
        }

        float ssum = 0.f;
        ull o[32];
        #pragma unroll
        for (int i = 0; i < 32; i++) o[i] = 0ULL;

        #pragma unroll 1
        for (int w = 0; w < WIN; w++) {
            const float* trow = s_tf + (tid + w) * STRIDE;   // global row gr0+tid+w-5
            ull tp[32];
            #pragma unroll
            for (int i = 0; i < 16; i++) {
                ulonglong2 t2 = *(const ulonglong2*)(trow + 4 * i);
                tp[2 * i] = t2.x; tp[2 * i + 1] = t2.y;
            }
            ull dp0 = 0, dp1 = 0, dp2 = 0, dp3 = 0;
            #pragma unroll
            for (int i = 0; i < 8; i++) {
                dp0 = fma2(tp[4 * i],     v1[4 * i],     dp0);
                dp1 = fma2(tp[4 * i + 1], v1[4 * i + 1], dp1);
                dp2 = fma2(tp[4 * i + 2], v1[4 * i + 2], dp2);
                dp3 = fma2(tp[4 * i + 3], v1[4 * i + 3], dp3);
            }
            ull dp = add2(add2(dp0, dp1), add2(dp2, dp3));
            float a, b; unpack2(dp, a, b);
            float e = __expf((a + b) * 0.125f);   // scores bounded -> max-free safe
            ssum += e;
            ull e2 = pack2(e, e);
            #pragma unroll
            for (int i = 0; i < 32; i++) o[i] = fma2(tp[i], e2, o[i]);
        }

        int gr = gr0 + tid;
        if (gr < nrows) {
            float rs = 1.f / ssum;
            #pragma unroll
            for (int i = 0; i < 16; i++) {
                float x, y, z, u;
                unpack2(o[2 * i], x, y); unpack2(o[2 * i + 1], z, u);
                float4 r = make_float4(x * rs, y * rs, z * rs, u * rs);
                *(float4*)(out + (size_t)gr * RANK + 4 * i) = r;
            }
        }
    }
}

extern "C" void kernel_launch(void* const* d_in, const int* in_sizes, int n_in,
                              void* d_out, int out_size)
{
    const float* tf = (const float*)d_in[0];   // (L, 64)
    const float* Wm = (const float*)d_in[1];   // (64, 64)
    const float* bv = (const float*)d_in[2];   // (64,)
    float* out = (float*)d_out;
    int nrows = in_sizes[0] / RANK;

    cudaFuncSetAttribute(attn_win_kernel,
                         cudaFuncAttributeMaxDynamicSharedMemorySize, SMEM_TOTAL);
    int grid = (nrows + TR - 1) / TR;
    attn_win_kernel<<<grid, NT, SMEM_TOTAL>>>(tf, Wm, bv, out, nrows);
}

// round 10
// speedup vs baseline: 1.8387x; 1.3344x over previous
#include <cuda_runtime.h>
#include <cuda_bf16.h>
#include <cstdint>
#include <math.h>

typedef unsigned long long ull;

#define RANK    64
#define WIN     11
#define PAD     5
#define TR      64
#define NT      128
#define STRIDEF 72
#define TFROWS  74            // TR + 2*PAD

// byte offsets in dynamic smem
#define OFF_TF   0            // [74][72] f32 = 21312
#define OFF_WH   21312        // [64][72] bf16 hi = 9216
#define OFF_WL   30528        // [64][72] bf16 lo = 9216
#define OFF_BIAS 39744        // 64 f32 = 256
#define SMEM_TOTAL 40000
#define WROW 144              // W tile row stride bytes

__device__ __forceinline__ ull pack2(float lo, float hi) {
    ull r; asm("mov.b64 %0,{%1,%2};" : "=l"(r) : "f"(lo), "f"(hi)); return r;
}
__device__ __forceinline__ void unpack2(ull v, float& lo, float& hi) {
    asm("mov.b64 {%0,%1},%2;" : "=f"(lo), "=f"(hi) : "l"(v));
}
__device__ __forceinline__ ull fma2(ull a, ull b, ull c) {
    ull d; asm("fma.rn.f32x2 %0,%1,%2,%3;" : "=l"(d) : "l"(a), "l"(b), "l"(c)); return d;
}
__device__ __forceinline__ ull add2(ull a, ull b) {
    ull d; asm("add.rn.f32x2 %0,%1,%2;" : "=l"(d) : "l"(a), "l"(b)); return d;
}
__device__ __forceinline__ uint32_t bf2(float lo, float hi) {
    uint32_t r; asm("cvt.rn.bf16x2.f32 %0, %1, %2;" : "=r"(r) : "f"(hi), "f"(lo)); return r;
}
__device__ __forceinline__ void split2(float f0, float f1, uint32_t& h, uint32_t& l) {
    h = bf2(f0, f1);
    float f0h = __uint_as_float(h << 16);
    float f1h = __uint_as_float(h & 0xffff0000u);
    l = bf2(f0 - f0h, f1 - f1h);
}
__device__ __forceinline__ float tanh_fast(float x) {
    float e = __expf(2.f * x);
    return 1.f - __fdividef(2.f, e + 1.f);
}

#define MMA(Cr, Ar, b0, b1)                                                    \
    asm volatile(                                                              \
        "mma.sync.aligned.m16n8k16.row.col.f32.bf16.bf16.f32 "                 \
        "{%0,%1,%2,%3},{%4,%5,%6,%7},{%8,%9},{%0,%1,%2,%3};"                   \
        : "+f"(Cr[0]), "+f"(Cr[1]), "+f"(Cr[2]), "+f"(Cr[3])                   \
        : "r"(Ar[0]), "r"(Ar[1]), "r"(Ar[2]), "r"(Ar[3]), "r"(b0), "r"(b1))

__global__ void __launch_bounds__(NT, 4)
attn_win_kernel(const float* __restrict__ tf, const float* __restrict__ Wm,
                const float* __restrict__ bv, float* __restrict__ out, int nrows)
{
    extern __shared__ char smem[];
    float* s_tf   = (float*)(smem + OFF_TF);
    float* s_bias = (float*)(smem + OFF_BIAS);
    const int tid  = threadIdx.x;
    const int wid  = tid >> 5;
    const int lane = tid & 31;
    const int g    = lane >> 2;      // quad id: fragment row group
    const int t    = lane & 3;       // thread-in-quad: channel group
    const int gr0  = blockIdx.x * TR;

    // ---- stage tf tile (fp32, zero-padded halo) ----
    for (int idx = tid; idx < TFROWS * 16; idx += NT) {
        int i = idx >> 4, q = idx & 15;
        int grow = gr0 - PAD + i;
        float4 v = make_float4(0.f, 0.f, 0.f, 0.f);
        if (grow >= 0 && grow < nrows)
            v = *(const float4*)(tf + (size_t)grow * RANK + 4 * q);
        *(float4*)(s_tf + i * STRIDEF + 4 * q) = v;
    }
    // ---- stage W hi/lo bf16 tiles ----
    for (int idx = tid; idx < 64 * 32; idx += NT) {
        int c = idx >> 5, kp = idx & 31;
        float2 wv = *(const float2*)(Wm + c * RANK + 2 * kp);
        uint32_t h, l; split2(wv.x, wv.y, h, l);
        *(uint32_t*)(smem + OFF_WH + c * WROW + kp * 4) = h;
        *(uint32_t*)(smem + OFF_WL + c * WROW + kp * 4) = l;
    }
    if (tid < RANK) s_bias[tid] = bv[tid];
    __syncthreads();   // the only block-wide sync

    // ---- phase 1: var1 = tf @ W^T via 3-term bf16-split HMMA ----
    // warp wid covers local rows 16*wid + {g, g+8}; C[nt][j]:
    //   j0,j1 -> row g cols 8nt+2t,+1 ; j2,j3 -> row g+8 same cols
    float C[8][4];
    #pragma unroll
    for (int nt = 0; nt < 8; nt++)
        #pragma unroll
        for (int j = 0; j < 4; j++) C[nt][j] = 0.f;

    #pragma unroll
    for (int ks = 0; ks < 4; ks++) {
        const float* a0p = s_tf + (16 * wid + g + PAD) * STRIDEF + ks * 16 + 2 * t;
        float2 a00 = *(const float2*)(a0p);
        float2 a10 = *(const float2*)(a0p + 8 * STRIDEF);
        float2 a01 = *(const float2*)(a0p + 8);
        float2 a11 = *(const float2*)(a0p + 8 * STRIDEF + 8);
        uint32_t AH[4], AL[4];
        split2(a00.x, a00.y, AH[0], AL[0]);
        split2(a10.x, a10.y, AH[1], AL[1]);
        split2(a01.x, a01.y, AH[2], AL[2]);
        split2(a11.x, a11.y, AH[3], AL[3]);
        #pragma unroll
        for (int nt = 0; nt < 8; nt++) {
            const char* wb = smem + OFF_WH + (nt * 8 + g) * WROW + (ks * 16 + 2 * t) * 2;
            uint32_t bh0 = *(const uint32_t*)(wb);
            uint32_t bh1 = *(const uint32_t*)(wb + 16);
            uint32_t bl0 = *(const uint32_t*)(wb + (OFF_WL - OFF_WH));
            uint32_t bl1 = *(const uint32_t*)(wb + (OFF_WL - OFF_WH) + 16);
            MMA(C[nt], AH, bh0, bh1);
            MMA(C[nt], AH, bl0, bl1);
            MMA(C[nt], AL, bh0, bh1);
        }
    }

    // ---- v1 = tanh(C + b), kept as packed f32 pairs in registers ----
    ull v1r[8], v1r8[8];
    #pragma unroll
    for (int nt = 0; nt < 8; nt++) {
        float2 bb = *(const float2*)(s_bias + 8 * nt + 2 * t);
        v1r[nt]  = pack2(tanh_fast(C[nt][0] + bb.x), tanh_fast(C[nt][1] + bb.y));
        v1r8[nt] = pack2(tanh_fast(C[nt][2] + bb.x), tanh_fast(C[nt][3] + bb.y));
    }

    // ---- phase 2: sliding window, quad-cooperative (2 rows per lane) ----
    const int r = 16 * wid + g;       // local row (and r+8)
    float ssum0 = 0.f, ssum1 = 0.f;
    ull o0[8], o1[8];
    #pragma unroll
    for (int nt = 0; nt < 8; nt++) { o0[nt] = 0ULL; o1[nt] = 0ULL; }

    // u = 0..18 slides over s_tf rows r..r+18; row r active u<=10, row r+8 active u>=8
    #pragma unroll
    for (int u = 0; u < 8; u++) {     // row r only
        const float* trow = s_tf + (r + u) * STRIDEF + 2 * t;
        ull tp[8];
        #pragma unroll
        for (int nt = 0; nt < 8; nt++) tp[nt] = *(const ull*)(trow + 8 * nt);
        ull da = 0, db = 0;
        #pragma unroll
        for (int i = 0; i < 4; i++) {
            da = fma2(tp[i], v1r[i], da);
            db = fma2(tp[i + 4], v1r[i + 4], db);
        }
        float x, y; unpack2(add2(da, db), x, y);
        float d = x + y;
        d += __shfl_xor_sync(0xffffffffu, d, 1);
        d += __shfl_xor_sync(0xffffffffu, d, 2);
        float e = __expf(d * 0.125f);
        ssum0 += e;
        ull e2 = pack2(e, e);
        #pragma unroll
        for (int nt = 0; nt < 8; nt++) o0[nt] = fma2(tp[nt], e2, o0[nt]);
    }
    #pragma unroll
    for (int u = 8; u < 11; u++) {    // both rows
        const float* trow = s_tf + (r + u) * STRIDEF + 2 * t;
        ull tp[8];
        #pragma unroll
        for (int nt = 0; nt < 8; nt++) tp[nt] = *(const ull*)(trow + 8 * nt);
        ull da = 0, db = 0, ca = 0, cb = 0;
        #pragma unroll
        for (int i = 0; i < 4; i++) {
            da = fma2(tp[i], v1r[i], da);
            db = fma2(tp[i + 4], v1r[i + 4], db);
            ca = fma2(tp[i], v1r8[i], ca);
            cb = fma2(tp[i + 4], v1r8[i + 4], cb);
        }
        float x, y; unpack2(add2(da, db), x, y);
        float p, q; unpack2(add2(ca, cb), p, q);
        ull dd = pack2(x + y, p + q);
        dd = add2(dd, __shfl_xor_sync(0xffffffffu, dd, 1));
        dd = add2(dd, __shfl_xor_sync(0xffffffffu, dd, 2));
        float d0, d1; unpack2(dd, d0, d1);
        float e0 = __expf(d0 * 0.125f);
        float e1 = __expf(d1 * 0.125f);
        ssum0 += e0; ssum1 += e1;
        ull ea = pack2(e0, e0), eb = pack2(e1, e1);
        #pragma unroll
        for (int nt = 0; nt < 8; nt++) {
            o0[nt] = fma2(tp[nt], ea, o0[nt]);
            o1[nt] = fma2(tp[nt], eb, o1[nt]);
        }
    }
    #pragma unroll
    for (int u = 11; u < 19; u++) {   // row r+8 only
        const float* trow = s_tf + (r + u) * STRIDEF + 2 * t;
        ull tp[8];
        #pragma unroll
        for (int nt = 0; nt < 8; nt++) tp[nt] = *(const ull*)(trow + 8 * nt);
        ull da = 0, db = 0;
        #pragma unroll
        for (int i = 0; i < 4; i++) {
            da = fma2(tp[i], v1r8[i], da);
            db = fma2(tp[i + 4], v1r8[i + 4], db);
        }
        float x, y; unpack2(add2(da, db), x, y);
        float d = x + y;
        d += __shfl_xor_sync(0xffffffffu, d, 1);
        d += __shfl_xor_sync(0xffffffffu, d, 2);
        float e = __expf(d * 0.125f);
        ssum1 += e;
        ull e2 = pack2(e, e);
        #pragma unroll
        for (int nt = 0; nt < 8; nt++) o1[nt] = fma2(tp[nt], e2, o1[nt]);
    }

    // ---- epilogue: normalize + store (lane writes its 16 channels of 2 rows) ----
    int gr = gr0 + r;
    if (gr < nrows) {
        float rs = 1.f / ssum0;
        #pragma unroll
        for (int nt = 0; nt < 8; nt++) {
            float x, y; unpack2(o0[nt], x, y);
            *(float2*)(out + (size_t)gr * RANK + 8 * nt + 2 * t) =
                make_float2(x * rs, y * rs);
        }
    }
    int gr8 = gr + 8;
    if (gr8 < nrows) {
        float rs = 1.f / ssum1;
        #pragma unroll
        for (int nt = 0; nt < 8; nt++) {
            float x, y; unpack2(o1[nt], x, y);
            *(float2*)(out + (size_t)gr8 * RANK + 8 * nt + 2 * t) =
                make_float2(x * rs, y * rs);
        }
    }
}

extern "C" void kernel_launch(void* const* d_in, const int* in_sizes, int n_in,
                              void* d_out, int out_size)
{
    const float* tf = (const float*)d_in[0];   // (L, 64)
    const float* Wm = (const float*)d_in[1];   // (64, 64)
    const float* bv = (const float*)d_in[2];   // (64,)
    float* out = (float*)d_out;
    int nrows = in_sizes[0] / RANK;

    cudaFuncSetAttribute(attn_win_kernel,
                         cudaFuncAttributeMaxDynamicSharedMemorySize, SMEM_TOTAL);
    int grid = (nrows + TR - 1) / TR;
    attn_win_kernel<<<grid, NT, SMEM_TOTAL>>>(tf, Wm, bv, out, nrows);
}

// round 15
// speedup vs baseline: 2.3461x; 1.2759x over previous
#include <cuda_runtime.h>
#include <cuda_bf16.h>
#include <cstdint>
#include <math.h>

#define RANK    64
#define PAD     5
#define TR      64
#define NT      128
#define TILROWS 80            // 74 used + 6 rows so MMA-padded reads stay in-bounds
#define RST     144           // row stride (bytes) for all bf16 tiles (72 bf16)

// smem byte offsets
#define OFF_RH   0            // tf hi: 80*144 = 11520
#define OFF_RL   11520        // tf lo            -> 23040
#define OFF_WH   23040        // W hi: 64*144 = 9216 -> 32256
#define OFF_WL   32256        // W lo             -> 41472
#define OFF_BIAS 41472        // 64 f32 = 256     -> 41728
#define SMEM_TOTAL 41728
#define HL 11520              // hi->lo tile delta

__device__ __forceinline__ uint32_t smem_u32(const void* p) {
    uint32_t a;
    asm("{ .reg .u64 t; cvta.to.shared.u64 t, %1; cvt.u32.u64 %0, t; }" : "=r"(a) : "l"(p));
    return a;
}
__device__ __forceinline__ uint32_t bf2(float lo, float hi) {
    uint32_t r; asm("cvt.rn.bf16x2.f32 %0, %1, %2;" : "=r"(r) : "f"(hi), "f"(lo)); return r;
}
__device__ __forceinline__ void split2(float f0, float f1, uint32_t& h, uint32_t& l) {
    h = bf2(f0, f1);
    float f0h = __uint_as_float(h << 16);
    float f1h = __uint_as_float(h & 0xffff0000u);
    l = bf2(f0 - f0h, f1 - f1h);
}
__device__ __forceinline__ float tanh_fast(float x) {
    float e = __expf(2.f * x);
    return 1.f - __fdividef(2.f, e + 1.f);
}
__device__ __forceinline__ void ldsm_x4(uint32_t* r, uint32_t a) {
    asm volatile("ldmatrix.sync.aligned.m8n8.x4.shared.b16 {%0,%1,%2,%3}, [%4];"
        : "=r"(r[0]), "=r"(r[1]), "=r"(r[2]), "=r"(r[3]) : "r"(a));
}
__device__ __forceinline__ void ldsm_x2(uint32_t& r0, uint32_t& r1, uint32_t a) {
    asm volatile("ldmatrix.sync.aligned.m8n8.x2.shared.b16 {%0,%1}, [%2];"
        : "=r"(r0), "=r"(r1) : "r"(a));
}
__device__ __forceinline__ void ldsm_x2t(uint32_t& r0, uint32_t& r1, uint32_t a) {
    asm volatile("ldmatrix.sync.aligned.m8n8.x2.trans.shared.b16 {%0,%1}, [%2];"
        : "=r"(r0), "=r"(r1) : "r"(a));
}

#define MMA(Cr, Ar, b0, b1)                                                    \
    asm volatile(                                                              \
        "mma.sync.aligned.m16n8k16.row.col.f32.bf16.bf16.f32 "                 \
        "{%0,%1,%2,%3},{%4,%5,%6,%7},{%8,%9},{%0,%1,%2,%3};"                   \
        : "+f"(Cr[0]), "+f"(Cr[1]), "+f"(Cr[2]), "+f"(Cr[3])                   \
        : "r"(Ar[0]), "r"(Ar[1]), "r"(Ar[2]), "r"(Ar[3]), "r"(b0), "r"(b1))

__global__ void __launch_bounds__(NT, 4)
attn_win_kernel(const float* __restrict__ tf, const float* __restrict__ Wm,
                const float* __restrict__ bv, float* __restrict__ out, int nrows)
{
    extern __shared__ char smem[];
    float* s_bias = (float*)(smem + OFF_BIAS);
    const uint32_t sb = smem_u32(smem);
    const int tid  = threadIdx.x;
    const int wid  = tid >> 5;
    const int lane = tid & 31;
    const int g    = lane >> 2;
    const int t    = lane & 3;
    const int gr0  = blockIdx.x * TR;

    // ---- stage tf bf16 hi/lo tiles (row-major, zero-padded halo) ----
    for (int idx = tid; idx < TILROWS * 16; idx += NT) {
        int i = idx >> 4, q = idx & 15;
        int grow = gr0 - PAD + i;
        float4 v = make_float4(0.f, 0.f, 0.f, 0.f);
        if (grow >= 0 && grow < nrows)
            v = *(const float4*)(tf + (size_t)grow * RANK + 4 * q);
        uint32_t h0, l0, h1, l1;
        split2(v.x, v.y, h0, l0);
        split2(v.z, v.w, h1, l1);
        *(uint2*)(smem + OFF_RH + i * RST + 8 * q) = make_uint2(h0, h1);
        *(uint2*)(smem + OFF_RL + i * RST + 8 * q) = make_uint2(l0, l1);
    }
    // ---- stage W hi/lo tiles ----
    for (int idx = tid; idx < 64 * 16; idx += NT) {
        int c = idx >> 4, q = idx & 15;
        float4 v = *(const float4*)(Wm + c * RANK + 4 * q);
        uint32_t h0, l0, h1, l1;
        split2(v.x, v.y, h0, l0);
        split2(v.z, v.w, h1, l1);
        *(uint2*)(smem + OFF_WH + c * RST + 8 * q) = make_uint2(h0, h1);
        *(uint2*)(smem + OFF_WL + c * RST + 8 * q) = make_uint2(l0, l1);
    }
    if (tid < RANK) s_bias[tid] = bv[tid];
    __syncthreads();

    // ---- phase 1: C = tf @ W^T (16 rows/warp), 3-term bf16-split HMMA ----
    float C[8][4];
    #pragma unroll
    for (int nt = 0; nt < 8; nt++)
        #pragma unroll
        for (int j = 0; j < 4; j++) C[nt][j] = 0.f;

    {
        uint32_t abase = sb + OFF_RH + (16 * wid + PAD + (lane & 15)) * RST
                         + ((lane & 16) ? 16 : 0);
        #pragma unroll
        for (int ks = 0; ks < 4; ks++) {
            uint32_t ah[4], al[4];
            ldsm_x4(ah, abase + ks * 32);
            ldsm_x4(al, abase + HL + ks * 32);
            #pragma unroll
            for (int nt = 0; nt < 8; nt++) {
                uint32_t wb = sb + OFF_WH + (nt * 8 + g) * RST + (ks * 16 + 2 * t) * 2;
                uint32_t bh0 = *(const uint32_t*)(smem + (wb - sb));
                uint32_t bh1 = *(const uint32_t*)(smem + (wb - sb) + 16);
                uint32_t bl0 = *(const uint32_t*)(smem + (wb - sb) + (OFF_WL - OFF_WH));
                uint32_t bl1 = *(const uint32_t*)(smem + (wb - sb) + (OFF_WL - OFF_WH) + 16);
                MMA(C[nt], ah, bh0, bh1);
                MMA(C[nt], ah, bl0, bl1);
                MMA(C[nt], al, bh0, bh1);
            }
        }
    }

    // ---- v1 = tanh(C + b) -> bf16 hi/lo A-fragment halves (rows g / g+8) ----
    uint32_t v1h_a[8], v1l_a[8], v1h_b[8], v1l_b[8];
    #pragma unroll
    for (int nt = 0; nt < 8; nt++) {
        float2 bb = *(const float2*)(s_bias + 8 * nt + 2 * t);
        float t0 = tanh_fast(C[nt][0] + bb.x);
        float t1 = tanh_fast(C[nt][1] + bb.y);
        float t2 = tanh_fast(C[nt][2] + bb.x);
        float t3 = tanh_fast(C[nt][3] + bb.y);
        split2(t0, t1, v1h_a[nt], v1l_a[nt]);
        split2(t2, t3, v1h_b[nt], v1l_b[nt]);
    }

    // ---- scores: S(16x32) = v1 @ TF_nbhd^T  (nbhd = tile rows 16wid..16wid+31) ----
    float S[4][4];
    #pragma unroll
    for (int nj = 0; nj < 4; nj++)
        #pragma unroll
        for (int j = 0; j < 4; j++) S[nj][j] = 0.f;
    {
        uint32_t brow = sb + OFF_RH + (16 * wid + (lane & 7)) * RST
                        + ((lane & 8) ? 16 : 0);
        #pragma unroll
        for (int nj = 0; nj < 4; nj++) {
            #pragma unroll
            for (int ks = 0; ks < 4; ks++) {
                uint32_t ad = brow + nj * 8 * RST + ks * 32;
                uint32_t bh0, bh1, bl0, bl1;
                ldsm_x2(bh0, bh1, ad);
                ldsm_x2(bl0, bl1, ad + HL);
                uint32_t ah[4] = { v1h_a[2 * ks], v1h_b[2 * ks],
                                   v1h_a[2 * ks + 1], v1h_b[2 * ks + 1] };
                uint32_t al[4] = { v1l_a[2 * ks], v1l_b[2 * ks],
                                   v1l_a[2 * ks + 1], v1l_b[2 * ks + 1] };
                MMA(S[nj], ah, bh0, bh1);
                MMA(S[nj], ah, bl0, bl1);
                MMA(S[nj], al, bh0, bh1);
            }
        }
    }

    // ---- band mask + exp + row sums (rows g and g+8) ----
    float e[4][4];
    float ss_a = 0.f, ss_b = 0.f;
    #pragma unroll
    for (int nj = 0; nj < 4; nj++) {
        int j0 = 8 * nj + 2 * t, j1 = j0 + 1;
        e[nj][0] = ((unsigned)(j0 - g) <= 10u)     ? __expf(S[nj][0] * 0.125f) : 0.f;
        e[nj][1] = ((unsigned)(j1 - g) <= 10u)     ? __expf(S[nj][1] * 0.125f) : 0.f;
        e[nj][2] = ((unsigned)(j0 - g - 8) <= 10u) ? __expf(S[nj][2] * 0.125f) : 0.f;
        e[nj][3] = ((unsigned)(j1 - g - 8) <= 10u) ? __expf(S[nj][3] * 0.125f) : 0.f;
        ss_a += e[nj][0] + e[nj][1];
        ss_b += e[nj][2] + e[nj][3];
    }
    ss_a += __shfl_xor_sync(0xffffffffu, ss_a, 1);
    ss_a += __shfl_xor_sync(0xffffffffu, ss_a, 2);
    ss_b += __shfl_xor_sync(0xffffffffu, ss_b, 1);
    ss_b += __shfl_xor_sync(0xffffffffu, ss_b, 2);

    // ---- P = e (unnormalized), S C-frag -> P A-frags, hi/lo split ----
    uint32_t ph[2][4], pl[2][4];
    #pragma unroll
    for (int s = 0; s < 2; s++) {
        split2(e[2 * s][0],     e[2 * s][1],     ph[s][0], pl[s][0]);
        split2(e[2 * s][2],     e[2 * s][3],     ph[s][1], pl[s][1]);
        split2(e[2 * s + 1][0], e[2 * s + 1][1], ph[s][2], pl[s][2]);
        split2(e[2 * s + 1][2], e[2 * s + 1][3], ph[s][3], pl[s][3]);
    }

    // ---- output: O(16x64) = P @ TF_nbhd  (B via ldmatrix.trans) ----
    float O[8][4];
    #pragma unroll
    for (int nt = 0; nt < 8; nt++)
        #pragma unroll
        for (int j = 0; j < 4; j++) O[nt][j] = 0.f;
    {
        uint32_t obase = sb + OFF_RH + (16 * wid + (lane & 15)) * RST;
        #pragma unroll
        for (int nt = 0; nt < 8; nt++) {
            #pragma unroll
            for (int s = 0; s < 2; s++) {
                uint32_t ad = obase + s * 16 * RST + nt * 16;
                uint32_t bh0, bh1, bl0, bl1;
                ldsm_x2t(bh0, bh1, ad);
                ldsm_x2t(bl0, bl1, ad + HL);
                MMA(O[nt], ph[s], bh0, bh1);
                MMA(O[nt], ph[s], bl0, bl1);
                MMA(O[nt], pl[s], bh0, bh1);
            }
        }
    }

    // ---- epilogue: normalize + store ----
    int gra = gr0 + 16 * wid + g;
    int grb = gra + 8;
    float rsa = 1.f / ss_a, rsb = 1.f / ss_b;
    if (gra < nrows) {
        #pragma unroll
        for (int nt = 0; nt < 8; nt++)
            *(float2*)(out + (size_t)gra * RANK + 8 * nt + 2 * t) =
                make_float2(O[nt][0] * rsa, O[nt][1] * rsa);
    }
    if (grb < nrows) {
        #pragma unroll
        for (int nt = 0; nt < 8; nt++)
            *(float2*)(out + (size_t)grb * RANK + 8 * nt + 2 * t) =
                make_float2(O[nt][2] * rsb, O[nt][3] * rsb);
    }
}

extern "C" void kernel_launch(void* const* d_in, const int* in_sizes, int n_in,
                              void* d_out, int out_size)
{
    const float* tf = (const float*)d_in[0];   // (L, 64)
    const float* Wm = (const float*)d_in[1];   // (64, 64)
    const float* bv = (const float*)d_in[2];   // (64,)
    float* out = (float*)d_out;
    int nrows = in_sizes[0] / RANK;

    cudaFuncSetAttribute(attn_win_kernel,
                         cudaFuncAttributeMaxDynamicSharedMemorySize, SMEM_TOTAL);
    int grid = (nrows + TR - 1) / TR;
    attn_win_kernel<<<grid, NT, SMEM_TOTAL>>>(tf, Wm, bv, out, nrows);
}

// round 17
// speedup vs baseline: 2.3975x; 1.0219x over previous
#include <cuda_runtime.h>
#include <cuda_bf16.h>
#include <cstdint>
#include <math.h>

#define RANK    64
#define PAD     5
#define TR      64
#define NT      128
#define TILROWS 80            // 74 used + 6 pad rows so 32-row nbhd reads stay in-bounds
#define RST     144           // row stride (bytes) for all bf16 tiles (72 bf16)

// smem byte offsets
#define OFF_RH   0            // tf hi: 80*144 = 11520
#define OFF_RL   11520        // tf lo            -> 23040
#define OFF_WH   23040        // W hi: 64*144 = 9216 -> 32256
#define OFF_WL   32256        // W lo             -> 41472
#define OFF_BIAS 41472        // 64 f32 = 256     -> 41728
#define SMEM_TOTAL 41728
#define HL  11520             // tf hi->lo tile delta
#define HLW 9216              // W  hi->lo tile delta

__device__ __forceinline__ uint32_t smem_u32(const void* p) {
    uint32_t a;
    asm("{ .reg .u64 t; cvta.to.shared.u64 t, %1; cvt.u32.u64 %0, t; }" : "=r"(a) : "l"(p));
    return a;
}
__device__ __forceinline__ uint32_t bf2(float lo, float hi) {
    uint32_t r; asm("cvt.rn.bf16x2.f32 %0, %1, %2;" : "=r"(r) : "f"(hi), "f"(lo)); return r;
}
__device__ __forceinline__ void split2(float f0, float f1, uint32_t& h, uint32_t& l) {
    h = bf2(f0, f1);
    float f0h = __uint_as_float(h << 16);
    float f1h = __uint_as_float(h & 0xffff0000u);
    l = bf2(f0 - f0h, f1 - f1h);
}
__device__ __forceinline__ float tanh_fast(float x) {
    float e = __expf(2.f * x);
    return 1.f - __fdividef(2.f, e + 1.f);
}
__device__ __forceinline__ void ldsm_x4(uint32_t* r, uint32_t a) {
    asm volatile("ldmatrix.sync.aligned.m8n8.x4.shared.b16 {%0,%1,%2,%3}, [%4];"
        : "=r"(r[0]), "=r"(r[1]), "=r"(r[2]), "=r"(r[3]) : "r"(a));
}
__device__ __forceinline__ void ldsm_x4t(uint32_t* r, uint32_t a) {
    asm volatile("ldmatrix.sync.aligned.m8n8.x4.trans.shared.b16 {%0,%1,%2,%3}, [%4];"
        : "=r"(r[0]), "=r"(r[1]), "=r"(r[2]), "=r"(r[3]) : "r"(a));
}

#define MMA(Cr, Ar, b0, b1)                                                    \
    asm volatile(                                                              \
        "mma.sync.aligned.m16n8k16.row.col.f32.bf16.bf16.f32 "                 \
        "{%0,%1,%2,%3},{%4,%5,%6,%7},{%8,%9},{%0,%1,%2,%3};"                   \
        : "+f"(Cr[0]), "+f"(Cr[1]), "+f"(Cr[2]), "+f"(Cr[3])                   \
        : "r"(Ar[0]), "r"(Ar[1]), "r"(Ar[2]), "r"(Ar[3]), "r"(b0), "r"(b1))

__global__ void __launch_bounds__(NT, 5)
attn_win_kernel(const float* __restrict__ tf, const float* __restrict__ Wm,
                const float* __restrict__ bv, float* __restrict__ out, int nrows)
{
    extern __shared__ char smem[];
    float* s_bias = (float*)(smem + OFF_BIAS);
    const uint32_t sb = smem_u32(smem);
    const int tid  = threadIdx.x;
    const int wid  = tid >> 5;
    const int lane = tid & 31;
    const int g    = lane >> 2;
    const int t    = lane & 3;
    const int gr0  = blockIdx.x * TR;

    // ---- stage tf bf16 hi/lo tiles (row-major, zero-padded halo) ----
    for (int idx = tid; idx < TILROWS * 16; idx += NT) {
        int i = idx >> 4, q = idx & 15;
        int grow = gr0 - PAD + i;
        float4 v = make_float4(0.f, 0.f, 0.f, 0.f);
        if (grow >= 0 && grow < nrows)
            v = *(const float4*)(tf + (size_t)grow * RANK + 4 * q);
        uint32_t h0, l0, h1, l1;
        split2(v.x, v.y, h0, l0);
        split2(v.z, v.w, h1, l1);
        *(uint2*)(smem + OFF_RH + i * RST + 8 * q) = make_uint2(h0, h1);
        *(uint2*)(smem + OFF_RL + i * RST + 8 * q) = make_uint2(l0, l1);
    }
    // ---- stage W hi/lo tiles ----
    for (int idx = tid; idx < 64 * 16; idx += NT) {
        int c = idx >> 4, q = idx & 15;
        float4 v = *(const float4*)(Wm + c * RANK + 4 * q);
        uint32_t h0, l0, h1, l1;
        split2(v.x, v.y, h0, l0);
        split2(v.z, v.w, h1, l1);
        *(uint2*)(smem + OFF_WH + c * RST + 8 * q) = make_uint2(h0, h1);
        *(uint2*)(smem + OFF_WL + c * RST + 8 * q) = make_uint2(l0, l1);
    }
    if (tid < RANK) s_bias[tid] = bv[tid];
    __syncthreads();

    // ---- phase 1: C = tf @ W^T (16 rows/warp), 3-term bf16-split HMMA ----
    // W B-frags via ldmatrix x4: mats {np rows 0-7 @k, +8 @k, rows 8-15 @k, +8}
    float C[8][4];
    #pragma unroll
    for (int nt = 0; nt < 8; nt++)
        #pragma unroll
        for (int j = 0; j < 4; j++) C[nt][j] = 0.f;
    {
        uint32_t abase = sb + OFF_RH + (16 * wid + PAD + (lane & 15)) * RST
                         + ((lane & 16) ? 16 : 0);
        uint32_t wbase = sb + OFF_WH + ((lane & 7) + ((lane & 16) >> 1)) * RST
                         + ((lane & 8) ? 16 : 0);
        #pragma unroll
        for (int ks = 0; ks < 4; ks++) {
            uint32_t ah[4], al[4];
            ldsm_x4(ah, abase + ks * 32);
            ldsm_x4(al, abase + HL + ks * 32);
            #pragma unroll
            for (int np = 0; np < 4; np++) {
                uint32_t wh[4], wl[4];
                ldsm_x4(wh, wbase + np * (16 * RST) + ks * 32);
                ldsm_x4(wl, wbase + HLW + np * (16 * RST) + ks * 32);
                MMA(C[2 * np],     ah, wh[0], wh[1]);
                MMA(C[2 * np],     ah, wl[0], wl[1]);
                MMA(C[2 * np],     al, wh[0], wh[1]);
                MMA(C[2 * np + 1], ah, wh[2], wh[3]);
                MMA(C[2 * np + 1], ah, wl[2], wl[3]);
                MMA(C[2 * np + 1], al, wh[2], wh[3]);
            }
        }
    }

    // ---- v1 = tanh(C + b) -> bf16 hi/lo A-fragment halves (rows g / g+8) ----
    uint32_t v1h_a[8], v1l_a[8], v1h_b[8], v1l_b[8];
    #pragma unroll
    for (int nt = 0; nt < 8; nt++) {
        float2 bb = *(const float2*)(s_bias + 8 * nt + 2 * t);
        float t0 = tanh_fast(C[nt][0] + bb.x);
        float t1 = tanh_fast(C[nt][1] + bb.y);
        float t2 = tanh_fast(C[nt][2] + bb.x);
        float t3 = tanh_fast(C[nt][3] + bb.y);
        split2(t0, t1, v1h_a[nt], v1l_a[nt]);
        split2(t2, t3, v1h_b[nt], v1l_b[nt]);
    }

    // ---- scores: S(16x32) = v1 @ TF_nbhd^T (x4 ldsm covers 2 K-steps) ----
    float S[4][4];
    #pragma unroll
    for (int nj = 0; nj < 4; nj++)
        #pragma unroll
        for (int j = 0; j < 4; j++) S[nj][j] = 0.f;
    {
        uint32_t sbase = sb + OFF_RH + (16 * wid + (lane & 7)) * RST + (lane >> 3) * 16;
        #pragma unroll
        for (int nj = 0; nj < 4; nj++) {
            #pragma unroll
            for (int k2 = 0; k2 < 2; k2++) {
                uint32_t bh[4], bl[4];
                uint32_t ad = sbase + nj * (8 * RST) + k2 * 64;
                ldsm_x4(bh, ad);
                ldsm_x4(bl, ad + HL);
                int ka = 2 * k2, kb = 2 * k2 + 1;
                uint32_t ah0[4] = { v1h_a[2 * ka], v1h_b[2 * ka],
                                    v1h_a[2 * ka + 1], v1h_b[2 * ka + 1] };
                uint32_t al0[4] = { v1l_a[2 * ka], v1l_b[2 * ka],
                                    v1l_a[2 * ka + 1], v1l_b[2 * ka + 1] };
                uint32_t ah1[4] = { v1h_a[2 * kb], v1h_b[2 * kb],
                                    v1h_a[2 * kb + 1], v1h_b[2 * kb + 1] };
                uint32_t al1[4] = { v1l_a[2 * kb], v1l_b[2 * kb],
                                    v1l_a[2 * kb + 1], v1l_b[2 * kb + 1] };
                MMA(S[nj], ah0, bh[0], bh[1]);
                MMA(S[nj], ah0, bl[0], bl[1]);
                MMA(S[nj], al0, bh[0], bh[1]);
                MMA(S[nj], ah1, bh[2], bh[3]);
                MMA(S[nj], ah1, bl[2], bl[3]);
                MMA(S[nj], al1, bh[2], bh[3]);
            }
        }
    }

    // ---- band mask + exp + row sums (rows g and g+8) ----
    float e[4][4];
    float ss_a = 0.f, ss_b = 0.f;
    #pragma unroll
    for (int nj = 0; nj < 4; nj++) {
        int j0 = 8 * nj + 2 * t, j1 = j0 + 1;
        e[nj][0] = ((unsigned)(j0 - g) <= 10u)     ? __expf(S[nj][0] * 0.125f) : 0.f;
        e[nj][1] = ((unsigned)(j1 - g) <= 10u)     ? __expf(S[nj][1] * 0.125f) : 0.f;
        e[nj][2] = ((unsigned)(j0 - g - 8) <= 10u) ? __expf(S[nj][2] * 0.125f) : 0.f;
        e[nj][3] = ((unsigned)(j1 - g - 8) <= 10u) ? __expf(S[nj][3] * 0.125f) : 0.f;
        ss_a += e[nj][0] + e[nj][1];
        ss_b += e[nj][2] + e[nj][3];
    }
    ss_a += __shfl_xor_sync(0xffffffffu, ss_a, 1);
    ss_a += __shfl_xor_sync(0xffffffffu, ss_a, 2);
    ss_b += __shfl_xor_sync(0xffffffffu, ss_b, 1);
    ss_b += __shfl_xor_sync(0xffffffffu, ss_b, 2);

    // ---- P = e (unnormalized), S C-frag -> P A-frags, hi/lo split ----
    uint32_t ph[2][4], pl[2][4];
    #pragma unroll
    for (int s = 0; s < 2; s++) {
        split2(e[2 * s][0],     e[2 * s][1],     ph[s][0], pl[s][0]);
        split2(e[2 * s][2],     e[2 * s][3],     ph[s][1], pl[s][1]);
        split2(e[2 * s + 1][0], e[2 * s + 1][1], ph[s][2], pl[s][2]);
        split2(e[2 * s + 1][2], e[2 * s + 1][3], ph[s][3], pl[s][3]);
    }

    // ---- output: O(16x64) = P @ TF_nbhd (x4 trans ldsm covers both s-halves) ----
    float O[8][4];
    #pragma unroll
    for (int nt = 0; nt < 8; nt++)
        #pragma unroll
        for (int j = 0; j < 4; j++) O[nt][j] = 0.f;
    {
        uint32_t obase = sb + OFF_RH + (16 * wid + lane) * RST;
        #pragma unroll
        for (int nt = 0; nt < 8; nt++) {
            uint32_t bh[4], bl[4];
            ldsm_x4t(bh, obase + nt * 16);
            ldsm_x4t(bl, obase + HL + nt * 16);
            MMA(O[nt], ph[0], bh[0], bh[1]);
            MMA(O[nt], ph[0], bl[0], bl[1]);
            MMA(O[nt], pl[0], bh[0], bh[1]);
            MMA(O[nt], ph[1], bh[2], bh[3]);
            MMA(O[nt], ph[1], bl[2], bl[3]);
            MMA(O[nt], pl[1], bh[2], bh[3]);
        }
    }

    // ---- epilogue: normalize + store ----
    int gra = gr0 + 16 * wid + g;
    int grb = gra + 8;
    float rsa = 1.f / ss_a, rsb = 1.f / ss_b;
    if (gra < nrows) {
        #pragma unroll
        for (int nt = 0; nt < 8; nt++)
            *(float2*)(out + (size_t)gra * RANK + 8 * nt + 2 * t) =
                make_float2(O[nt][0] * rsa, O[nt][1] * rsa);
    }
    if (grb < nrows) {
        #pragma unroll
        for (int nt = 0; nt < 8; nt++)
            *(float2*)(out + (size_t)grb * RANK + 8 * nt + 2 * t) =
                make_float2(O[nt][2] * rsb, O[nt][3] * rsb);
    }
}

extern "C" void kernel_launch(void* const* d_in, const int* in_sizes, int n_in,
                              void* d_out, int out_size)
{
    const float* tf = (const float*)d_in[0];   // (L, 64)
    const float* Wm = (const float*)d_in[1];   // (64, 64)
    const float* bv = (const float*)d_in[2];   // (64,)
    float* out = (float*)d_out;
    int nrows = in_sizes[0] / RANK;

    cudaFuncSetAttribute(attn_win_kernel,
                         cudaFuncAttributeMaxDynamicSharedMemorySize, SMEM_TOTAL);
    int grid = (nrows + TR - 1) / TR;
    attn_win_kernel<<<grid, NT, SMEM_TOTAL>>>(tf, Wm, bv, out, nrows);
}